// round 10
// baseline (speedup 1.0000x reference)
#include <cuda_runtime.h>
#include <cuda_bf16.h>
#include <cstdint>

// SimplifiedMambaBlock: the reference SSM scan has no input-injection term
// (h0 = 0, h <- exp(dt*A) * h), so h == 0 always => result == x exactly.
// Optimal kernel = copy x -> d_out (33.5 MB fp32).
//
// R9: resubmit of R8 (container infra failed twice; experiment untested).
// SM/CE/TMA all floor at ~10.4-11us => mixed R/W HBM rate (~6.4 TB/s) is
// the limiter. Remove the DRAM READ stream: mark only x's lines
// L2::evict_last (33.5 MB fits in the 126 MB L2, re-read every graph
// replay) and stream the stores with st.global.cs (evict-first — d_out is
// never read during timing, its dirty lines are pure pollution). R4/R5
// failed because BOTH streams were marked evict_last (67 MB protected ->
// thrash). Steady-state target: reads from L2, writes-only DRAM.

__global__ __launch_bounds__(256) void mamba_copy_ldlast_stcs(
    const uint32_t* __restrict__ src, uint32_t* __restrict__ dst, int n8)
{
    // n8 = count of 32-byte chunks. Each thread copies 2 chunks.
    int base = blockIdx.x * (blockDim.x * 2) + threadIdx.x;

    #pragma unroll
    for (int k = 0; k < 2; k++) {
        int i = base + k * blockDim.x;
        if (i < n8) {
            const uint32_t* s = src + 8 * (size_t)i;
            uint32_t* d = dst + 8 * (size_t)i;

            uint32_t r0, r1, r2, r3, r4, r5, r6, r7;
            // 32B read, keep in L2 across replays
            asm volatile(
                "ld.global.L2::evict_last.v8.b32 {%0,%1,%2,%3,%4,%5,%6,%7}, [%8];"
                : "=r"(r0), "=r"(r1), "=r"(r2), "=r"(r3),
                  "=r"(r4), "=r"(r5), "=r"(r6), "=r"(r7)
                : "l"(s));
            // streaming stores, evict-first (2 x 16B)
            asm volatile(
                "st.global.cs.v4.b32 [%0], {%1,%2,%3,%4};"
                :: "l"(d), "r"(r0), "r"(r1), "r"(r2), "r"(r3) : "memory");
            asm volatile(
                "st.global.cs.v4.b32 [%0], {%1,%2,%3,%4};"
                :: "l"(d + 4), "r"(r4), "r"(r5), "r"(r6), "r"(r7) : "memory");
        }
    }
}

extern "C" void kernel_launch(void* const* d_in, const int* in_sizes, int n_in,
                              void* d_out, int out_size)
{
    const uint32_t* x = (const uint32_t*)d_in[0];   // (B, L, dim) fp32
    uint32_t* out = (uint32_t*)d_out;

    int n8 = out_size >> 3;                   // 1048576 chunks of 32 B
    int threads = 256;
    int per_block = threads * 2;
    int blocks = (n8 + per_block - 1) / per_block;  // 2048

    mamba_copy_ldlast_stcs<<<blocks, threads>>>(x, out, n8);
}

// round 11
// speedup vs baseline: 1.8309x; 1.8309x over previous
#include <cuda_runtime.h>
#include <cuda_bf16.h>

// SimplifiedMambaBlock: the reference SSM scan has no input-injection term
// (h0 = 0, h <- exp(dt*A) * h), so h == 0 for all timesteps, ssm_out == 0,
// y == 0, out_proj(0) == 0, and the result is exactly `x + residual == x`.
// Exact-optimal kernel = copy x -> d_out (33.5 MB fp32, rel_err = 0).
//
// FINAL (R2 config): across 7 probes, SM-LDG / copy-engine / TMA all
// converge at 10.4-11.0 us; evict_last policies are neutral and streaming
// (.cs) stores are 2x WORSE (they forfeit L2 write coalescing). The floor
// is the memory system's sustained mixed R/W rate (~6.4 TB/s for 1:1
// read/write turnaround) + ~1 us launch overhead: 67 MB / 6.4 TB/s ~= 10.4
// us. This config (4x float4 per thread, 2048 blocks, front-batched loads)
// was the best measured: 10.43 us.

__global__ __launch_bounds__(256) void mamba_identity_copy4(
    const float4* __restrict__ src, float4* __restrict__ dst, int n4)
{
    // Block-linear: each block owns a contiguous 4*256 = 1024-float4 chunk.
    int base = blockIdx.x * (blockDim.x * 4) + threadIdx.x;

    if (base + 3 * blockDim.x < n4) {
        // Fast path: 4 independent loads issued back-to-back (MLP=4).
        float4 a = src[base];
        float4 b = src[base + blockDim.x];
        float4 c = src[base + 2 * blockDim.x];
        float4 d = src[base + 3 * blockDim.x];
        dst[base]                  = a;
        dst[base + blockDim.x]     = b;
        dst[base + 2 * blockDim.x] = c;
        dst[base + 3 * blockDim.x] = d;
    } else {
        #pragma unroll
        for (int k = 0; k < 4; k++) {
            int i = base + k * blockDim.x;
            if (i < n4) dst[i] = src[i];
        }
    }
}

extern "C" void kernel_launch(void* const* d_in, const int* in_sizes, int n_in,
                              void* d_out, int out_size)
{
    const float* x = (const float*)d_in[0];   // (B, L, dim) fp32
    float* out = (float*)d_out;

    int n4 = out_size >> 2;                   // 2097152 float4
    int threads = 256;
    int per_block = threads * 4;              // 1024 float4 per block
    int blocks = (n4 + per_block - 1) / per_block;  // 2048

    mamba_identity_copy4<<<blocks, threads>>>(
        (const float4*)x, (float4*)out, n4);
}